// round 12
// baseline (speedup 1.0000x reference)
#include <cuda_runtime.h>
#include <cstdint>

// ============================================================================
// CapLayerLP PDIP QP (n=1024, m=2051): diag + rank-2 KKT -> Woodbury (2x2).
// Cluster of 8 CTAs x 128 threads (1 coord/thread). FULL FP32, 3 fused
// reduce rounds/iter.
//
// Round-12 (bisect of R11's failure): KEEP the sync-free per-warp push
// all-reduce (packed u64 st.async, no __syncthreads, 32-entry butterfly
// combine), REVERT rcp.approx -> exact IEEE 1.0f/x (the only numeric delta
// vs the passing R10). If this passes, rcp.approx was the R11 bug.
// ============================================================================

#define CL    8
#define T     128
#define NWARP 4
#define NE    (CL*NWARP)      // 32 mailbox entries
#define NV    1024
#define IMCON (1.0f/2051.0f)
#define EPSR  1e-4f
#define CCAP  10.0f
#define ITERS 20

__device__ __forceinline__ uint32_t s2u(const void* p) {
    uint32_t a;
    asm("{ .reg .u64 t; cvta.to.shared.u64 t, %1; cvt.u32.u64 %0, t; }" : "=r"(a) : "l"(p));
    return a;
}
__device__ __forceinline__ uint32_t cta_rank() {
    uint32_t r; asm("mov.u32 %0, %%cluster_ctarank;" : "=r"(r)); return r;
}
__device__ __forceinline__ uint32_t mapa_u32(uint32_t a, uint32_t r) {
    uint32_t ra;
    asm("mapa.shared::cluster.u32 %0, %1, %2;" : "=r"(ra) : "r"(a), "r"(r));
    return ra;
}
__device__ __forceinline__ void mb_init(uint32_t a, uint32_t cnt) {
    asm volatile("mbarrier.init.shared.b64 [%0], %1;" :: "r"(a), "r"(cnt) : "memory");
}
__device__ __forceinline__ void mb_expect(uint32_t a, uint32_t bytes) {
    asm volatile("mbarrier.arrive.expect_tx.shared.b64 _, [%0], %1;"
                 :: "r"(a), "r"(bytes) : "memory");
}
__device__ __forceinline__ void mb_wait(uint32_t a, uint32_t ph) {
    asm volatile(
        "{\n\t.reg .pred P;\n\t"
        "WL_%=:\n\t"
        "mbarrier.try_wait.parity.acquire.cta.shared::cta.b64 P, [%0], %1, 0x989680;\n\t"
        "@P bra.uni WD_%=;\n\t"
        "bra.uni WL_%=;\n\t"
        "WD_%=:\n\t}"
        :: "r"(a), "r"(ph) : "memory");
}
__device__ __forceinline__ void st_async_u64(uint32_t ra, uint64_t v, uint32_t rb) {
    asm volatile("st.async.shared::cluster.mbarrier::complete_tx::bytes.u64 [%0], %1, [%2];"
                 :: "r"(ra), "l"(v), "r"(rb) : "memory");
}
__device__ __forceinline__ void st_async_f(uint32_t ra, float v, uint32_t rb) {
    asm volatile("st.async.shared::cluster.mbarrier::complete_tx::bytes.b32 [%0], %1, [%2];"
                 :: "r"(ra), "r"(__float_as_uint(v)), "r"(rb) : "memory");
}
__device__ __forceinline__ uint64_t pack2(float a, float b) {
    return ((uint64_t)__float_as_uint(b) << 32) | (uint64_t)__float_as_uint(a);
}

// warp butterfly sum/max: ALL lanes end with the total
__device__ __forceinline__ float bsum(float v) {
#pragma unroll
    for (int o = 16; o > 0; o >>= 1) v += __shfl_xor_sync(0xffffffffu, v, o);
    return v;
}
__device__ __forceinline__ float bmax(float v) {
#pragma unroll
    for (int o = 16; o > 0; o >>= 1) v = fmaxf(v, __shfl_xor_sync(0xffffffffu, v, o));
    return v;
}

__global__ void __launch_bounds__(T, 1) __cluster_dims__(CL, 1, 1)
pdip_kernel(const float* __restrict__ xin, const int* __restrict__ male,
            float* __restrict__ out)
{
    const uint32_t rank = cta_rank();
    const int i    = threadIdx.x;
    const int lane = i & 31;
    const int wid  = i >> 5;
    const int pr   = lane & 7;        // destination rank for this lane's push
    const int pp   = lane >> 3;       // slot-pair index this lane pushes

    __shared__ __align__(8) float2 m1[NE][4];
    __shared__ __align__(8) float2 m2[NE][3];
    __shared__ __align__(8) float2 m3[NE][2];
    __shared__ float mI[NE];
    __shared__ __align__(8) unsigned long long mbar[4];

    const uint32_t bar1 = s2u(&mbar[0]);
    const uint32_t bar2 = s2u(&mbar[1]);
    const uint32_t bar3 = s2u(&mbar[2]);
    const uint32_t barI = s2u(&mbar[3]);

    if (i == 0) {
        mb_init(bar1, 1); mb_init(bar2, 1); mb_init(bar3, 1); mb_init(barI, 1);
        mb_expect(barI, NE * 4);
        asm volatile("fence.mbarrier_init.release.cluster;" ::: "memory");
    }
    __syncthreads();
    asm volatile("barrier.cluster.arrive.aligned;" ::: "memory");
    asm volatile("barrier.cluster.wait.aligned;" ::: "memory");

    const int c = (int)rank * T + i;
    const float pi = -xin[c];
    const float fi = (float)male[c];
    float xi = 0.0f, s1 = 1.0f, z1 = 1.0f, s2 = 1.0f, z2 = 1.0f;

    const int e = (int)rank * NWARP + wid;   // this warp's mailbox entry

    // ---- init all-reduce: n_male ----
    {
        float v = bsum(fi);
        if (lane < CL) {
            uint32_t rb = mapa_u32(barI, lane);
            uint32_t ra = mapa_u32(s2u(&mI[e]), lane);
            st_async_f(ra, v, rb);
        }
        mb_wait(barI, 0);
    }
    float nm;
    {
        float v = mI[lane];
        nm = bsum(v);
    }
    const float hA = CCAP * nm * (1.0f/(float)NV) + 1.0f;
    const float hB = -(CCAP * nm * (1.0f/(float)NV));

    float s0 = 1.0f, sA = 1.0f, sB = 1.0f;
    float z0 = 1.0f, zA = 1.0f, zB = 1.0f;

    for (int it = 0; it < ITERS; ++it) {
        const uint32_t ph = (uint32_t)(it & 1);
        if (i == 0) {
            mb_expect(bar1, NE*4*8);
            mb_expect(bar2, NE*3*8);
            mb_expect(bar3, NE*2*8);
        }

        // scalar reciprocals (prev-state only) -- exact IEEE division
        const float is0 = 1.0f/s0, isA = 1.0f/sA, isB = 1.0f/sB;
        const float w0 = z0 * is0, wA = zA * isA, wB = zB * isB;
        const float M11p = s0 / z0;
        const float M22p = 1.0f / (wA + wB);

        // ================= Round 1 (diag sums + predictor base) ============
        const float ss    = s1 * s2;
        const float invss = 1.0f / ss;
        const float invs1 = s2 * invss;
        const float invs2 = s1 * invss;
        const float den   = fmaf(EPSR, ss, fmaf(z1, s2, z2 * s1));
        const float invD  = ss / den;
        const float rp1 = s1 - xi;
        const float rp2 = xi + s2 - 1.0f;
        const float w1  = z1 * invs1;
        const float w2  = z2 * invs2;
        const float rx  = EPSR*xi + pi + (z0 - z1 + z2 + fi*(zA - zB));
        const float t1v = w1*rp1 - z1;
        const float t2v = w2*rp2 - z2;
        const float gbase = -(rx - t1v + t2v) * invD;
        {
            float v0 = bsum(xi);
            float v1 = bsum(fi * xi);
            float v2 = bsum(s1 * z1 + s2 * z2);
            float v3 = bsum(invD);
            float v4 = bsum(fi * invD);
            float v5 = bsum(gbase);
            float v6 = bsum(fi * gbase);
            float a = (pp == 0) ? v0 : (pp == 1) ? v2 : (pp == 2) ? v4 : v6;
            float b = (pp == 0) ? v1 : (pp == 1) ? v3 : (pp == 2) ? v5 : 0.0f;
            uint32_t rb = mapa_u32(bar1, pr);
            uint32_t ra = mapa_u32(s2u(&m1[e][pp]), pr);
            st_async_u64(ra, pack2(a, b), rb);
        }
        mb_wait(bar1, ph);
        float sumx, fx, szv, SiD, SfD, Sg0, Sfg0;
        {
            float2 a0 = m1[lane][0], a1 = m1[lane][1], a2 = m1[lane][2], a3 = m1[lane][3];
            sumx = a0.x; fx = a0.y; szv = a1.x; SiD = a1.y;
            SfD = a2.x; Sg0 = a2.y; Sfg0 = a3.x;
#pragma unroll
            for (int o = 16; o > 0; o >>= 1) {
                sumx += __shfl_xor_sync(0xffffffffu, sumx, o);
                fx   += __shfl_xor_sync(0xffffffffu, fx,   o);
                szv  += __shfl_xor_sync(0xffffffffu, szv,  o);
                SiD  += __shfl_xor_sync(0xffffffffu, SiD,  o);
                SfD  += __shfl_xor_sync(0xffffffffu, SfD,  o);
                Sg0  += __shfl_xor_sync(0xffffffffu, Sg0,  o);
                Sfg0 += __shfl_xor_sync(0xffffffffu, Sfg0, o);
            }
        }

        // post-round-1 scalar algebra
        const float rp0 = sumx + s0 - CCAP;
        const float rpA =  fx + sA - hA;
        const float rpB = -fx + sB - hB;
        const float SZTOT = szv + s0*z0 + sA*zA + sB*zB;
        const float mu  = SZTOT * IMCON;
        const float imu = 1.0f / mu;
        const float T0 = w0*rp0 - z0;
        const float TA = wA*rpA - zA;
        const float TB = wB*rpB - zB;
        const float TAB = TA - TB;
        const float M11 = M11p + SiD;
        const float M22 = M22p + SfD;
        const float M12 = SfD;
        const float detinv = 1.0f / (M11*M22 - M12*M12);
        const float u1 = Sg0  - T0*SiD - TAB*SfD;
        const float uf = Sfg0 - (T0 + TAB)*SfD;
        const float Y1 = (M22*u1 - M12*uf) * detinv;
        const float Y2 = (M11*uf - M12*u1) * detinv;
        const float sdx = u1 - Y1*SiD - Y2*SfD;
        const float fdx = uf - (Y1 + Y2)*SfD;
        const float ds0 = -rp0 - sdx;
        const float dsA = -rpA - fdx;
        const float dsB = -rpB + fdx;
        const float dz0 = -z0 - w0*ds0;
        const float dzA = -zA - wA*dsA;
        const float dzB = -zB - wB*dsB;
        float sc_q = fmaxf(fmaxf(-ds0,0.0f)*is0, fmaxf(fmaxf(-dsA,0.0f)*isA, fmaxf(-dsB,0.0f)*isB));
        sc_q = fmaxf(sc_q, fmaxf(1.0f + ds0*is0, 0.0f));
        sc_q = fmaxf(sc_q, fmaxf(1.0f + dsA*isA, 0.0f));
        sc_q = fmaxf(sc_q, fmaxf(1.0f + dsB*isB, 0.0f));

        // ========= Round 2 (affine step/mu_aff + corrector base) ===========
        float prod1, prod2, gcb, cw;
        {
            float g  = gbase - (T0 + fi*TAB) * invD;
            float dx = g - (Y1 + fi*Y2) * invD;
            float ds1 = dx - rp1,  ds2 = -rp2 - dx;
            float dz1 = -z1 - w1*ds1;
            float dz2 = -z2 - w2*ds2;
            float r1 = ds1 * invs1, r2 = ds2 * invs2;
            float mq = fmaxf(sc_q, fmaxf(fmaxf(-r1, 0.0f), fmaxf(-r2, 0.0f)));
            mq = fmaxf(mq, fmaxf(fmaxf(1.0f + r1, 0.0f), fmaxf(1.0f + r2, 0.0f)));
            prod1 = ds1 * dz1;
            prod2 = ds2 * dz2;
            float t1b = (z1*rp1 - s1*z1 - prod1) * invs1;
            float t2b = (z2*rp2 - s2*z2 - prod2) * invs2;
            gcb = -(rx + t2b - t1b) * invD;
            cw  = (invs2 - invs1) * invD;
            float v0 = bsum(prod1 + prod2);
            float v1 = bmax(mq);
            float v2 = bsum(gcb);
            float v3 = bsum(fi * gcb);
            float v4 = bsum(cw);
            float v5 = bsum(fi * cw);
            if (pp < 3) {
                float a = (pp == 0) ? v0 : (pp == 1) ? v2 : v4;
                float b = (pp == 0) ? v1 : (pp == 1) ? v3 : v5;
                uint32_t rb = mapa_u32(bar2, pr);
                uint32_t ra = mapa_u32(s2u(&m2[e][pp]), pr);
                st_async_u64(ra, pack2(a, b), rb);
            }
        }
        mb_wait(bar2, ph);
        float S2v, qmax, Sgc, Sfgc, Scw, Sfcw;
        {
            float2 a0 = m2[lane][0], a1 = m2[lane][1], a2 = m2[lane][2];
            S2v = a0.x; qmax = a0.y; Sgc = a1.x; Sfgc = a1.y; Scw = a2.x; Sfcw = a2.y;
#pragma unroll
            for (int o = 16; o > 0; o >>= 1) {
                S2v  += __shfl_xor_sync(0xffffffffu, S2v,  o);
                qmax  = fmaxf(qmax, __shfl_xor_sync(0xffffffffu, qmax, o));
                Sgc  += __shfl_xor_sync(0xffffffffu, Sgc,  o);
                Sfgc += __shfl_xor_sync(0xffffffffu, Sfgc, o);
                Scw  += __shfl_xor_sync(0xffffffffu, Scw,  o);
                Sfcw += __shfl_xor_sync(0xffffffffu, Sfcw, o);
            }
        }

        // post-round-2 scalar algebra
        const float aaff = (qmax > 0.0f) ? fminf(1.0f, 1.0f / qmax) : 1.0f;
        const float S2t  = S2v + ds0*dz0 + dsA*dzA + dsB*dzB;
        const float muaff = fmaf(aaff*aaff, S2t, SZTOT*(1.0f - aaff)) * IMCON;
        const float smu = muaff * muaff * muaff * (imu * imu);
        const float rsz0 = s0*z0 + ds0*dz0 - smu;
        const float rszA = sA*zA + dsA*dzA - smu;
        const float rszB = sB*zB + dsB*dzB - smu;
        const float T0c = (z0*rp0 - rsz0) * is0;
        const float TAc = (zA*rpA - rszA) * isA;
        const float TBc = (zB*rpB - rszB) * isB;
        const float TABc = TAc - TBc;
        const float u1c = Sgc  - T0c*SiD - TABc*SfD - smu*Scw;
        const float ufc = Sfgc - (T0c + TABc)*SfD   - smu*Sfcw;
        const float Y1c = (M22*u1c - M12*ufc) * detinv;
        const float Y2c = (M11*ufc - M12*u1c) * detinv;
        const float sdxc = u1c - Y1c*SiD - Y2c*SfD;
        const float fdxc = ufc - (Y1c + Y2c)*SfD;
        const float ds0c = -rp0 - sdxc;
        const float dsAc = -rpA - fdxc;
        const float dsBc = -rpB + fdxc;
        const float dz0c = -(rsz0 + z0*ds0c) * is0;
        const float dzAc = -(rszA + zA*dsAc) * isA;
        const float dzBc = -(rszB + zB*dsBc) * isB;
        float sc_qs = fmaxf(fmaxf(-ds0c,0.0f)*is0,
                      fmaxf(fmaxf(-dsAc,0.0f)*isA, fmaxf(-dsBc,0.0f)*isB));
        float scn = fmaxf(-dz0c, 0.0f), scd = z0;
        { float n2 = fmaxf(-dzAc,0.0f), d2 = zA; if (n2*scd > scn*d2) { scn=n2; scd=d2; } }
        { float n2 = fmaxf(-dzBc,0.0f), d2 = zB; if (n2*scd > scn*d2) { scn=n2; scd=d2; } }

        // ================= Round 3 (corrector dir + step) =================
        float dxc, ds1c, ds2c, dz1c, dz2c;
        const float rsz1 = s1*z1 + prod1 - smu;
        const float rsz2 = s2*z2 + prod2 - smu;
        {
            float gc = gcb - (T0c + fi*TABc)*invD - smu*cw;
            dxc  = gc - (Y1c + fi*Y2c) * invD;
            ds1c = dxc - rp1;
            ds2c = -rp2 - dxc;
            dz1c = -(rsz1 + z1*ds1c) * invs1;
            dz2c = -(rsz2 + z2*ds2c) * invs2;
            float mqs = fmaxf(sc_qs, fmaxf(fmaxf(-ds1c,0.0f)*invs1, fmaxf(-ds2c,0.0f)*invs2));
            float n1 = fmaxf(-dz1c, 0.0f), d1v = z1;
            float n2 = fmaxf(-dz2c, 0.0f), d2v = z2;
            if (n2*d1v > n1*d2v) { n1 = n2; d1v = d2v; }
            float pn = scn, pd = scd;
            if (n1*pd > pn*d1v)  { pn = n1; pd = d1v; }
            mqs = bmax(mqs);
#pragma unroll
            for (int o = 16; o > 0; o >>= 1) {
                float nn = __shfl_xor_sync(0xffffffffu, pn, o);
                float dd = __shfl_xor_sync(0xffffffffu, pd, o);
                if (nn * pd > pn * dd) { pn = nn; pd = dd; }
            }
            if (pp < 2) {
                float a = (pp == 0) ? mqs : pd;
                float b = (pp == 0) ? pn  : 0.0f;
                uint32_t rb = mapa_u32(bar3, pr);
                uint32_t ra = mapa_u32(s2u(&m3[e][pp]), pr);
                st_async_u64(ra, pack2(a, b), rb);
            }
        }
        mb_wait(bar3, ph);
        float mqs, pn, pd;
        {
            float2 a0 = m3[lane][0], a1 = m3[lane][1];
            mqs = a0.x; pn = a0.y; pd = a1.x;
#pragma unroll
            for (int o = 16; o > 0; o >>= 1) {
                mqs = fmaxf(mqs, __shfl_xor_sync(0xffffffffu, mqs, o));
                float nn = __shfl_xor_sync(0xffffffffu, pn, o);
                float dd = __shfl_xor_sync(0xffffffffu, pd, o);
                if (nn * pd > pn * dd) { pn = nn; pd = dd; }
            }
        }

        if (mqs * pd > pn) { pn = mqs; pd = 1.0f; }
        const float st = (pn > 0.0f) ? fminf(1.0f, pd / pn) : 1.0f;
        const float alpha = 0.99f * st;

        s0 += alpha*ds0c;  sA += alpha*dsAc;  sB += alpha*dsBc;
        z0 += alpha*dz0c;  zA += alpha*dzAc;  zB += alpha*dzBc;
        xi += alpha*dxc;
        s1 += alpha*ds1c;  z1 += alpha*dz1c;
        s2 += alpha*ds2c;  z2 += alpha*dz2c;
    }

    out[c] = xi;
}

extern "C" void kernel_launch(void* const* d_in, const int* in_sizes, int n_in,
                              void* d_out, int out_size)
{
    const float* x    = (const float*)d_in[0];
    const int*   male = (const int*)d_in[1];
    float*       out  = (float*)d_out;
    pdip_kernel<<<CL, T>>>(x, male, out);
}

// round 13
// speedup vs baseline: 1.0913x; 1.0913x over previous
#include <cuda_runtime.h>
#include <cstdint>

// ============================================================================
// CapLayerLP PDIP QP (n=1024, m=2051): diag + rank-2 KKT -> Woodbury (2x2).
// Cluster of 8 CTAs x 128 threads (1 coord/thread). FULL FP32, 3 fused
// reduce rounds/iter, sync-free per-warp st.async push all-reduce (R12).
//
// Round-13:
//  * Newton-refined reciprocal (rcp.approx + 1 NR step, <=1ulp -- the IEEE-
//    rounding class R12 tolerates, NOT R11's raw approx) on every critical-
//    path reciprocal: invss, invD, detinv, imu, aaff, final step.
//  * invz1/invz2 (NR) + iz0/izA/izB hoisted to iteration start -> round 3
//    step max is a plain fmax reduce (pair-max machinery deleted), one b32
//    push slot, one combine butterfly.
// ============================================================================

#define CL    8
#define T     128
#define NWARP 4
#define NE    (CL*NWARP)      // 32 mailbox entries
#define NV    1024
#define IMCON (1.0f/2051.0f)
#define EPSR  1e-4f
#define CCAP  10.0f
#define ITERS 20

// Newton-refined reciprocal: rcp.approx (2^-22) + 1 NR step -> <=1 ulp.
__device__ __forceinline__ float nrcp(float x) {
    float r; asm("rcp.approx.f32 %0, %1;" : "=f"(r) : "f"(x));
    r = r * fmaf(-x, r, 2.0f);
    return r;
}

__device__ __forceinline__ uint32_t s2u(const void* p) {
    uint32_t a;
    asm("{ .reg .u64 t; cvta.to.shared.u64 t, %1; cvt.u32.u64 %0, t; }" : "=r"(a) : "l"(p));
    return a;
}
__device__ __forceinline__ uint32_t cta_rank() {
    uint32_t r; asm("mov.u32 %0, %%cluster_ctarank;" : "=r"(r)); return r;
}
__device__ __forceinline__ uint32_t mapa_u32(uint32_t a, uint32_t r) {
    uint32_t ra;
    asm("mapa.shared::cluster.u32 %0, %1, %2;" : "=r"(ra) : "r"(a), "r"(r));
    return ra;
}
__device__ __forceinline__ void mb_init(uint32_t a, uint32_t cnt) {
    asm volatile("mbarrier.init.shared.b64 [%0], %1;" :: "r"(a), "r"(cnt) : "memory");
}
__device__ __forceinline__ void mb_expect(uint32_t a, uint32_t bytes) {
    asm volatile("mbarrier.arrive.expect_tx.shared.b64 _, [%0], %1;"
                 :: "r"(a), "r"(bytes) : "memory");
}
__device__ __forceinline__ void mb_wait(uint32_t a, uint32_t ph) {
    asm volatile(
        "{\n\t.reg .pred P;\n\t"
        "WL_%=:\n\t"
        "mbarrier.try_wait.parity.acquire.cta.shared::cta.b64 P, [%0], %1, 0x989680;\n\t"
        "@P bra.uni WD_%=;\n\t"
        "bra.uni WL_%=;\n\t"
        "WD_%=:\n\t}"
        :: "r"(a), "r"(ph) : "memory");
}
__device__ __forceinline__ void st_async_u64(uint32_t ra, uint64_t v, uint32_t rb) {
    asm volatile("st.async.shared::cluster.mbarrier::complete_tx::bytes.u64 [%0], %1, [%2];"
                 :: "r"(ra), "l"(v), "r"(rb) : "memory");
}
__device__ __forceinline__ void st_async_f(uint32_t ra, float v, uint32_t rb) {
    asm volatile("st.async.shared::cluster.mbarrier::complete_tx::bytes.b32 [%0], %1, [%2];"
                 :: "r"(ra), "r"(__float_as_uint(v)), "r"(rb) : "memory");
}
__device__ __forceinline__ uint64_t pack2(float a, float b) {
    return ((uint64_t)__float_as_uint(b) << 32) | (uint64_t)__float_as_uint(a);
}

__device__ __forceinline__ float bsum(float v) {
#pragma unroll
    for (int o = 16; o > 0; o >>= 1) v += __shfl_xor_sync(0xffffffffu, v, o);
    return v;
}
__device__ __forceinline__ float bmax(float v) {
#pragma unroll
    for (int o = 16; o > 0; o >>= 1) v = fmaxf(v, __shfl_xor_sync(0xffffffffu, v, o));
    return v;
}

__global__ void __launch_bounds__(T, 1) __cluster_dims__(CL, 1, 1)
pdip_kernel(const float* __restrict__ xin, const int* __restrict__ male,
            float* __restrict__ out)
{
    const uint32_t rank = cta_rank();
    const int i    = threadIdx.x;
    const int lane = i & 31;
    const int wid  = i >> 5;
    const int pr   = lane & 7;        // destination rank for this lane's push
    const int pp   = lane >> 3;       // slot-pair index this lane pushes

    __shared__ __align__(8) float2 m1[NE][4];
    __shared__ __align__(8) float2 m2[NE][3];
    __shared__ float m3[NE];
    __shared__ float mI[NE];
    __shared__ __align__(8) unsigned long long mbar[4];

    const uint32_t bar1 = s2u(&mbar[0]);
    const uint32_t bar2 = s2u(&mbar[1]);
    const uint32_t bar3 = s2u(&mbar[2]);
    const uint32_t barI = s2u(&mbar[3]);

    if (i == 0) {
        mb_init(bar1, 1); mb_init(bar2, 1); mb_init(bar3, 1); mb_init(barI, 1);
        mb_expect(barI, NE * 4);
        asm volatile("fence.mbarrier_init.release.cluster;" ::: "memory");
    }
    __syncthreads();
    asm volatile("barrier.cluster.arrive.aligned;" ::: "memory");
    asm volatile("barrier.cluster.wait.aligned;" ::: "memory");

    const int c = (int)rank * T + i;
    const float pi = -xin[c];
    const float fi = (float)male[c];
    float xi = 0.0f, s1 = 1.0f, z1 = 1.0f, s2 = 1.0f, z2 = 1.0f;

    const int e = (int)rank * NWARP + wid;   // this warp's mailbox entry

    // ---- init all-reduce: n_male ----
    {
        float v = bsum(fi);
        if (lane < CL) {
            uint32_t rb = mapa_u32(barI, lane);
            uint32_t ra = mapa_u32(s2u(&mI[e]), lane);
            st_async_f(ra, v, rb);
        }
        mb_wait(barI, 0);
    }
    float nm;
    {
        float v = mI[lane];
        nm = bsum(v);
    }
    const float hA = CCAP * nm * (1.0f/(float)NV) + 1.0f;
    const float hB = -(CCAP * nm * (1.0f/(float)NV));

    float s0 = 1.0f, sA = 1.0f, sB = 1.0f;
    float z0 = 1.0f, zA = 1.0f, zB = 1.0f;

    for (int it = 0; it < ITERS; ++it) {
        const uint32_t ph = (uint32_t)(it & 1);
        if (i == 0) {
            mb_expect(bar1, NE*4*8);
            mb_expect(bar2, NE*3*8);
            mb_expect(bar3, NE*4);
        }

        // scalar reciprocals (prev-state only; off critical path -> IEEE)
        const float is0 = 1.0f/s0, isA = 1.0f/sA, isB = 1.0f/sB;
        const float iz0 = 1.0f/z0, izA = 1.0f/zA, izB = 1.0f/zB;
        const float w0 = z0 * is0, wA = zA * isA, wB = zB * isB;
        const float M11p = s0 / z0;
        const float M22p = 1.0f / (wA + wB);

        // ================= Round 1 (diag sums + predictor base) ============
        const float ss    = s1 * s2;
        const float invss = nrcp(ss);
        const float invs1 = s2 * invss;
        const float invs2 = s1 * invss;
        const float den   = fmaf(EPSR, ss, fmaf(z1, s2, z2 * s1));
        const float invD  = ss * nrcp(den);
        const float invz1 = nrcp(z1);          // hoisted for round 3
        const float invz2 = nrcp(z2);
        const float rp1 = s1 - xi;
        const float rp2 = xi + s2 - 1.0f;
        const float w1  = z1 * invs1;
        const float w2  = z2 * invs2;
        const float rx  = EPSR*xi + pi + (z0 - z1 + z2 + fi*(zA - zB));
        const float t1v = w1*rp1 - z1;
        const float t2v = w2*rp2 - z2;
        const float gbase = -(rx - t1v + t2v) * invD;
        {
            float v0 = bsum(xi);
            float v1 = bsum(fi * xi);
            float v2 = bsum(s1 * z1 + s2 * z2);
            float v3 = bsum(invD);
            float v4 = bsum(fi * invD);
            float v5 = bsum(gbase);
            float v6 = bsum(fi * gbase);
            float a = (pp == 0) ? v0 : (pp == 1) ? v2 : (pp == 2) ? v4 : v6;
            float b = (pp == 0) ? v1 : (pp == 1) ? v3 : (pp == 2) ? v5 : 0.0f;
            uint32_t rb = mapa_u32(bar1, pr);
            uint32_t ra = mapa_u32(s2u(&m1[e][pp]), pr);
            st_async_u64(ra, pack2(a, b), rb);
        }
        mb_wait(bar1, ph);
        float sumx, fx, szv, SiD, SfD, Sg0, Sfg0;
        {
            float2 a0 = m1[lane][0], a1 = m1[lane][1], a2 = m1[lane][2], a3 = m1[lane][3];
            sumx = a0.x; fx = a0.y; szv = a1.x; SiD = a1.y;
            SfD = a2.x; Sg0 = a2.y; Sfg0 = a3.x;
#pragma unroll
            for (int o = 16; o > 0; o >>= 1) {
                sumx += __shfl_xor_sync(0xffffffffu, sumx, o);
                fx   += __shfl_xor_sync(0xffffffffu, fx,   o);
                szv  += __shfl_xor_sync(0xffffffffu, szv,  o);
                SiD  += __shfl_xor_sync(0xffffffffu, SiD,  o);
                SfD  += __shfl_xor_sync(0xffffffffu, SfD,  o);
                Sg0  += __shfl_xor_sync(0xffffffffu, Sg0,  o);
                Sfg0 += __shfl_xor_sync(0xffffffffu, Sfg0, o);
            }
        }

        // post-round-1 scalar algebra
        const float rp0 = sumx + s0 - CCAP;
        const float rpA =  fx + sA - hA;
        const float rpB = -fx + sB - hB;
        const float SZTOT = szv + s0*z0 + sA*zA + sB*zB;
        const float mu  = SZTOT * IMCON;
        const float imu = nrcp(mu);
        const float T0 = w0*rp0 - z0;
        const float TA = wA*rpA - zA;
        const float TB = wB*rpB - zB;
        const float TAB = TA - TB;
        const float M11 = M11p + SiD;
        const float M22 = M22p + SfD;
        const float M12 = SfD;
        const float detinv = nrcp(M11*M22 - M12*M12);
        const float u1 = Sg0  - T0*SiD - TAB*SfD;
        const float uf = Sfg0 - (T0 + TAB)*SfD;
        const float Y1 = (M22*u1 - M12*uf) * detinv;
        const float Y2 = (M11*uf - M12*u1) * detinv;
        const float sdx = u1 - Y1*SiD - Y2*SfD;
        const float fdx = uf - (Y1 + Y2)*SfD;
        const float ds0 = -rp0 - sdx;
        const float dsA = -rpA - fdx;
        const float dsB = -rpB + fdx;
        const float dz0 = -z0 - w0*ds0;
        const float dzA = -zA - wA*dsA;
        const float dzB = -zB - wB*dsB;
        float sc_q = fmaxf(fmaxf(-ds0,0.0f)*is0, fmaxf(fmaxf(-dsA,0.0f)*isA, fmaxf(-dsB,0.0f)*isB));
        sc_q = fmaxf(sc_q, fmaxf(1.0f + ds0*is0, 0.0f));
        sc_q = fmaxf(sc_q, fmaxf(1.0f + dsA*isA, 0.0f));
        sc_q = fmaxf(sc_q, fmaxf(1.0f + dsB*isB, 0.0f));

        // ========= Round 2 (affine step/mu_aff + corrector base) ===========
        float prod1, prod2, gcb, cw;
        {
            float g  = gbase - (T0 + fi*TAB) * invD;
            float dx = g - (Y1 + fi*Y2) * invD;
            float ds1 = dx - rp1,  ds2 = -rp2 - dx;
            float dz1 = -z1 - w1*ds1;
            float dz2 = -z2 - w2*ds2;
            float r1 = ds1 * invs1, r2 = ds2 * invs2;
            float mq = fmaxf(sc_q, fmaxf(fmaxf(-r1, 0.0f), fmaxf(-r2, 0.0f)));
            mq = fmaxf(mq, fmaxf(fmaxf(1.0f + r1, 0.0f), fmaxf(1.0f + r2, 0.0f)));
            prod1 = ds1 * dz1;
            prod2 = ds2 * dz2;
            float t1b = (z1*rp1 - s1*z1 - prod1) * invs1;
            float t2b = (z2*rp2 - s2*z2 - prod2) * invs2;
            gcb = -(rx + t2b - t1b) * invD;
            cw  = (invs2 - invs1) * invD;
            float v0 = bsum(prod1 + prod2);
            float v1 = bmax(mq);
            float v2 = bsum(gcb);
            float v3 = bsum(fi * gcb);
            float v4 = bsum(cw);
            float v5 = bsum(fi * cw);
            if (pp < 3) {
                float a = (pp == 0) ? v0 : (pp == 1) ? v2 : v4;
                float b = (pp == 0) ? v1 : (pp == 1) ? v3 : v5;
                uint32_t rb = mapa_u32(bar2, pr);
                uint32_t ra = mapa_u32(s2u(&m2[e][pp]), pr);
                st_async_u64(ra, pack2(a, b), rb);
            }
        }
        mb_wait(bar2, ph);
        float S2v, qmax, Sgc, Sfgc, Scw, Sfcw;
        {
            float2 a0 = m2[lane][0], a1 = m2[lane][1], a2 = m2[lane][2];
            S2v = a0.x; qmax = a0.y; Sgc = a1.x; Sfgc = a1.y; Scw = a2.x; Sfcw = a2.y;
#pragma unroll
            for (int o = 16; o > 0; o >>= 1) {
                S2v  += __shfl_xor_sync(0xffffffffu, S2v,  o);
                qmax  = fmaxf(qmax, __shfl_xor_sync(0xffffffffu, qmax, o));
                Sgc  += __shfl_xor_sync(0xffffffffu, Sgc,  o);
                Sfgc += __shfl_xor_sync(0xffffffffu, Sfgc, o);
                Scw  += __shfl_xor_sync(0xffffffffu, Scw,  o);
                Sfcw += __shfl_xor_sync(0xffffffffu, Sfcw, o);
            }
        }

        // post-round-2 scalar algebra
        const float aaff = (qmax > 0.0f) ? fminf(1.0f, nrcp(qmax)) : 1.0f;
        const float S2t  = S2v + ds0*dz0 + dsA*dzA + dsB*dzB;
        const float muaff = fmaf(aaff*aaff, S2t, SZTOT*(1.0f - aaff)) * IMCON;
        const float smu = muaff * muaff * muaff * (imu * imu);
        const float rsz0 = s0*z0 + ds0*dz0 - smu;
        const float rszA = sA*zA + dsA*dzA - smu;
        const float rszB = sB*zB + dsB*dzB - smu;
        const float T0c = (z0*rp0 - rsz0) * is0;
        const float TAc = (zA*rpA - rszA) * isA;
        const float TBc = (zB*rpB - rszB) * isB;
        const float TABc = TAc - TBc;
        const float u1c = Sgc  - T0c*SiD - TABc*SfD - smu*Scw;
        const float ufc = Sfgc - (T0c + TABc)*SfD   - smu*Sfcw;
        const float Y1c = (M22*u1c - M12*ufc) * detinv;
        const float Y2c = (M11*ufc - M12*u1c) * detinv;
        const float sdxc = u1c - Y1c*SiD - Y2c*SfD;
        const float fdxc = ufc - (Y1c + Y2c)*SfD;
        const float ds0c = -rp0 - sdxc;
        const float dsAc = -rpA - fdxc;
        const float dsBc = -rpB + fdxc;
        const float dz0c = -(rsz0 + z0*ds0c) * is0;
        const float dzAc = -(rszA + zA*dsAc) * isA;
        const float dzBc = -(rszB + zB*dsBc) * isB;
        float sc_q3 = fmaxf(fmaxf(-ds0c,0.0f)*is0,
                      fmaxf(fmaxf(-dsAc,0.0f)*isA, fmaxf(-dsBc,0.0f)*isB));
        sc_q3 = fmaxf(sc_q3, fmaxf(-dz0c,0.0f)*iz0);
        sc_q3 = fmaxf(sc_q3, fmaxf(-dzAc,0.0f)*izA);
        sc_q3 = fmaxf(sc_q3, fmaxf(-dzBc,0.0f)*izB);

        // ================= Round 3 (corrector dir + step, plain max) =======
        float dxc, ds1c, ds2c, dz1c, dz2c;
        const float rsz1 = s1*z1 + prod1 - smu;
        const float rsz2 = s2*z2 + prod2 - smu;
        {
            float gc = gcb - (T0c + fi*TABc)*invD - smu*cw;
            dxc  = gc - (Y1c + fi*Y2c) * invD;
            ds1c = dxc - rp1;
            ds2c = -rp2 - dxc;
            dz1c = -(rsz1 + z1*ds1c) * invs1;
            dz2c = -(rsz2 + z2*ds2c) * invs2;
            float qc = fmaxf(sc_q3, fmaxf(fmaxf(-ds1c,0.0f)*invs1, fmaxf(-ds2c,0.0f)*invs2));
            qc = fmaxf(qc, fmaxf(fmaxf(-dz1c,0.0f)*invz1, fmaxf(-dz2c,0.0f)*invz2));
            qc = bmax(qc);
            if (lane < CL) {
                uint32_t rb = mapa_u32(bar3, lane);
                uint32_t ra = mapa_u32(s2u(&m3[e]), lane);
                st_async_f(ra, qc, rb);
            }
        }
        mb_wait(bar3, ph);
        float q;
        {
            float v = m3[lane];
            q = bmax(v);
        }

        const float st = (q > 0.0f) ? fminf(1.0f, nrcp(q)) : 1.0f;
        const float alpha = 0.99f * st;

        s0 += alpha*ds0c;  sA += alpha*dsAc;  sB += alpha*dsBc;
        z0 += alpha*dz0c;  zA += alpha*dzAc;  zB += alpha*dzBc;
        xi += alpha*dxc;
        s1 += alpha*ds1c;  z1 += alpha*dz1c;
        s2 += alpha*ds2c;  z2 += alpha*dz2c;
    }

    out[c] = xi;
}

extern "C" void kernel_launch(void* const* d_in, const int* in_sizes, int n_in,
                              void* d_out, int out_size)
{
    const float* x    = (const float*)d_in[0];
    const int*   male = (const int*)d_in[1];
    float*       out  = (float*)d_out;
    pdip_kernel<<<CL, T>>>(x, male, out);
}

// round 15
// speedup vs baseline: 1.0988x; 1.0069x over previous
#include <cuda_runtime.h>
#include <cstdint>

// ============================================================================
// CapLayerLP PDIP QP (n=1024, m=2051): diag + rank-2 KKT -> Woodbury (2x2).
//
// Round-15 (= R14 with the compile error fixed): ONE CTA, 256 thr x 4 coords.
// The 8-CTA cluster existed for fp64 throughput (R5); in fp32 the vector work
// is trivial and every round paid DSMEM st.async (~215cyc) + mbarrier wakeup
// (~60-90cyc). Intra-CTA reduction is STS + BAR(~47) + LDS(~29). Same R13
// math: 3 fused reduce rounds/iter, nrcp (NR-refined, <=1ulp), hoisted invz.
// ============================================================================

#define T     256
#define VPT   4
#define NW    8               // warps
#define NV    1024
#define IMCON (1.0f/2051.0f)
#define EPSR  1e-4f
#define CCAP  10.0f
#define ITERS 20

// Newton-refined reciprocal: rcp.approx (2^-22) + 1 NR step -> <=1 ulp.
__device__ __forceinline__ float nrcp(float x) {
    float r; asm("rcp.approx.f32 %0, %1;" : "=f"(r) : "f"(x));
    r = r * fmaf(-x, r, 2.0f);
    return r;
}

// warp butterfly sum/max: ALL lanes end with the total
__device__ __forceinline__ float bsum(float v) {
#pragma unroll
    for (int o = 16; o > 0; o >>= 1) v += __shfl_xor_sync(0xffffffffu, v, o);
    return v;
}
__device__ __forceinline__ float bmax(float v) {
#pragma unroll
    for (int o = 16; o > 0; o >>= 1) v = fmaxf(v, __shfl_xor_sync(0xffffffffu, v, o));
    return v;
}

#define TREE8(W, s) ((((W)[0][s]+(W)[1][s])+((W)[2][s]+(W)[3][s])) + \
                     (((W)[4][s]+(W)[5][s])+((W)[6][s]+(W)[7][s])))
#define TREE8MAX(W, s) fmaxf(fmaxf(fmaxf((W)[0][s],(W)[1][s]),fmaxf((W)[2][s],(W)[3][s])), \
                             fmaxf(fmaxf((W)[4][s],(W)[5][s]),fmaxf((W)[6][s],(W)[7][s])))

__global__ void __launch_bounds__(T, 1)
pdip_kernel(const float* __restrict__ xin, const int* __restrict__ male,
            float* __restrict__ out)
{
    const int i    = threadIdx.x;
    const int lane = i & 31;
    const int wid  = i >> 5;

    __shared__ float w1[NW][7];
    __shared__ float w2[NW][6];
    __shared__ float w3[NW];
    __shared__ float wI[NW];

    float pi[VPT], fi[VPT];
    float xi[VPT], s1[VPT], z1[VPT], s2[VPT], z2[VPT];
#pragma unroll
    for (int k = 0; k < VPT; ++k) {
        int c = i + k * T;
        pi[k] = -xin[c];
        fi[k] = (float)male[c];
        xi[k] = 0.0f; s1[k] = 1.0f; z1[k] = 1.0f; s2[k] = 1.0f; z2[k] = 1.0f;
    }

    // ---- init: n_male ----
    {
        float v = bsum(fi[0] + fi[1] + fi[2] + fi[3]);
        if (lane == 0) wI[wid] = v;
    }
    __syncthreads();
    const float nmv = ((wI[0]+wI[1])+(wI[2]+wI[3])) + ((wI[4]+wI[5])+(wI[6]+wI[7]));
    const float hA = CCAP * nmv * (1.0f/(float)NV) + 1.0f;
    const float hB = -(CCAP * nmv * (1.0f/(float)NV));

    float s0 = 1.0f, sA = 1.0f, sB = 1.0f;
    float z0 = 1.0f, zA = 1.0f, zB = 1.0f;

    for (int it = 0; it < ITERS; ++it) {
        // scalar reciprocals (prev-state only; off the reduce critical path)
        const float is0 = 1.0f/s0, isA = 1.0f/sA, isB = 1.0f/sB;
        const float iz0 = 1.0f/z0, izA = 1.0f/zA, izB = 1.0f/zB;
        const float w0 = z0 * is0, wA = zA * isA, wB = zB * isB;
        const float M11p = s0 / z0;
        const float M22p = 1.0f / (wA + wB);

        // ================= Round 1 (diag sums + predictor base) ============
        float invs1[VPT], invs2[VPT], invD[VPT], invz1[VPT], invz2[VPT];
        float rp1[VPT], rp2[VPT], rx[VPT], gbase[VPT];
        {
            float v0=0, v1=0, v2=0, v3=0, v4=0, v5=0, v6=0;
#pragma unroll
            for (int k = 0; k < VPT; ++k) {
                float ss    = s1[k] * s2[k];
                float invss = nrcp(ss);
                invs1[k] = s2[k] * invss;
                invs2[k] = s1[k] * invss;
                float den = fmaf(EPSR, ss, fmaf(z1[k], s2[k], z2[k] * s1[k]));
                invD[k]  = ss * nrcp(den);
                invz1[k] = nrcp(z1[k]);
                invz2[k] = nrcp(z2[k]);
                rp1[k] = s1[k] - xi[k];
                rp2[k] = xi[k] + s2[k] - 1.0f;
                float w1v = z1[k] * invs1[k];
                float w2v = z2[k] * invs2[k];
                rx[k] = EPSR*xi[k] + pi[k] + (z0 - z1[k] + z2[k] + fi[k]*(zA - zB));
                float t1v = w1v*rp1[k] - z1[k];
                float t2v = w2v*rp2[k] - z2[k];
                gbase[k] = -(rx[k] - t1v + t2v) * invD[k];
                v0 += xi[k];
                v1 += fi[k] * xi[k];
                v2 += s1[k]*z1[k] + s2[k]*z2[k];
                v3 += invD[k];
                v4 += fi[k] * invD[k];
                v5 += gbase[k];
                v6 += fi[k] * gbase[k];
            }
            v0 = bsum(v0); v1 = bsum(v1); v2 = bsum(v2); v3 = bsum(v3);
            v4 = bsum(v4); v5 = bsum(v5); v6 = bsum(v6);
            if (lane == 0) {
                w1[wid][0]=v0; w1[wid][1]=v1; w1[wid][2]=v2; w1[wid][3]=v3;
                w1[wid][4]=v4; w1[wid][5]=v5; w1[wid][6]=v6;
            }
        }
        __syncthreads();
        const float sumx = TREE8(w1, 0);
        const float fx   = TREE8(w1, 1);
        const float szv  = TREE8(w1, 2);
        const float SiD  = TREE8(w1, 3);
        const float SfD  = TREE8(w1, 4);
        const float Sg0  = TREE8(w1, 5);
        const float Sfg0 = TREE8(w1, 6);

        // post-round-1 scalar algebra
        const float rp0 = sumx + s0 - CCAP;
        const float rpA =  fx + sA - hA;
        const float rpB = -fx + sB - hB;
        const float SZTOT = szv + s0*z0 + sA*zA + sB*zB;
        const float mu  = SZTOT * IMCON;
        const float imu = nrcp(mu);
        const float T0 = w0*rp0 - z0;
        const float TA = wA*rpA - zA;
        const float TB = wB*rpB - zB;
        const float TAB = TA - TB;
        const float M11 = M11p + SiD;
        const float M22 = M22p + SfD;
        const float M12 = SfD;
        const float detinv = nrcp(M11*M22 - M12*M12);
        const float u1 = Sg0  - T0*SiD - TAB*SfD;
        const float uf = Sfg0 - (T0 + TAB)*SfD;
        const float Y1 = (M22*u1 - M12*uf) * detinv;
        const float Y2 = (M11*uf - M12*u1) * detinv;
        const float sdx = u1 - Y1*SiD - Y2*SfD;
        const float fdx = uf - (Y1 + Y2)*SfD;
        const float ds0 = -rp0 - sdx;
        const float dsA = -rpA - fdx;
        const float dsB = -rpB + fdx;
        const float dz0 = -z0 - w0*ds0;
        const float dzA = -zA - wA*dsA;
        const float dzB = -zB - wB*dsB;
        float sc_q = fmaxf(fmaxf(-ds0,0.0f)*is0, fmaxf(fmaxf(-dsA,0.0f)*isA, fmaxf(-dsB,0.0f)*isB));
        sc_q = fmaxf(sc_q, fmaxf(1.0f + ds0*is0, 0.0f));
        sc_q = fmaxf(sc_q, fmaxf(1.0f + dsA*isA, 0.0f));
        sc_q = fmaxf(sc_q, fmaxf(1.0f + dsB*isB, 0.0f));

        // ========= Round 2 (affine step/mu_aff + corrector base) ===========
        float prod1[VPT], prod2[VPT], gcb[VPT], cw[VPT];
        {
            float v0 = 0, v2 = 0, v3 = 0, v4 = 0, v5 = 0;
            float mq = sc_q;
#pragma unroll
            for (int k = 0; k < VPT; ++k) {
                float g  = gbase[k] - (T0 + fi[k]*TAB) * invD[k];
                float dx = g - (Y1 + fi[k]*Y2) * invD[k];
                float w1v = z1[k] * invs1[k];
                float w2v = z2[k] * invs2[k];
                float ds1 = dx - rp1[k],  ds2 = -rp2[k] - dx;
                float dz1 = -z1[k] - w1v*ds1;
                float dz2 = -z2[k] - w2v*ds2;
                float r1 = ds1 * invs1[k], r2 = ds2 * invs2[k];
                mq = fmaxf(mq, fmaxf(fmaxf(-r1, 0.0f), fmaxf(-r2, 0.0f)));
                mq = fmaxf(mq, fmaxf(fmaxf(1.0f + r1, 0.0f), fmaxf(1.0f + r2, 0.0f)));
                prod1[k] = ds1 * dz1;
                prod2[k] = ds2 * dz2;
                float t1b = (z1[k]*rp1[k] - s1[k]*z1[k] - prod1[k]) * invs1[k];
                float t2b = (z2[k]*rp2[k] - s2[k]*z2[k] - prod2[k]) * invs2[k];
                gcb[k] = -(rx[k] + t2b - t1b) * invD[k];
                cw[k]  = (invs2[k] - invs1[k]) * invD[k];
                v0 += prod1[k] + prod2[k];
                v2 += gcb[k];
                v3 += fi[k] * gcb[k];
                v4 += cw[k];
                v5 += fi[k] * cw[k];
            }
            v0 = bsum(v0); mq = bmax(mq); v2 = bsum(v2);
            v3 = bsum(v3); v4 = bsum(v4); v5 = bsum(v5);
            if (lane == 0) {
                w2[wid][0]=v0; w2[wid][1]=mq; w2[wid][2]=v2;
                w2[wid][3]=v3; w2[wid][4]=v4; w2[wid][5]=v5;
            }
        }
        __syncthreads();
        const float S2v  = TREE8(w2, 0);
        const float qmax = TREE8MAX(w2, 1);
        const float Sgc  = TREE8(w2, 2);
        const float Sfgc = TREE8(w2, 3);
        const float Scw  = TREE8(w2, 4);
        const float Sfcw = TREE8(w2, 5);

        // post-round-2 scalar algebra
        const float aaff = (qmax > 0.0f) ? fminf(1.0f, nrcp(qmax)) : 1.0f;
        const float S2t  = S2v + ds0*dz0 + dsA*dzA + dsB*dzB;
        const float muaff = fmaf(aaff*aaff, S2t, SZTOT*(1.0f - aaff)) * IMCON;
        const float smu = muaff * muaff * muaff * (imu * imu);
        const float rsz0 = s0*z0 + ds0*dz0 - smu;
        const float rszA = sA*zA + dsA*dzA - smu;
        const float rszB = sB*zB + dsB*dzB - smu;
        const float T0c = (z0*rp0 - rsz0) * is0;
        const float TAc = (zA*rpA - rszA) * isA;
        const float TBc = (zB*rpB - rszB) * isB;
        const float TABc = TAc - TBc;
        const float u1c = Sgc  - T0c*SiD - TABc*SfD - smu*Scw;
        const float ufc = Sfgc - (T0c + TABc)*SfD   - smu*Sfcw;
        const float Y1c = (M22*u1c - M12*ufc) * detinv;
        const float Y2c = (M11*ufc - M12*u1c) * detinv;
        const float sdxc = u1c - Y1c*SiD - Y2c*SfD;
        const float fdxc = ufc - (Y1c + Y2c)*SfD;
        const float ds0c = -rp0 - sdxc;
        const float dsAc = -rpA - fdxc;
        const float dsBc = -rpB + fdxc;
        const float dz0c = -(rsz0 + z0*ds0c) * is0;
        const float dzAc = -(rszA + zA*dsAc) * isA;
        const float dzBc = -(rszB + zB*dsBc) * isB;
        float sc_q3 = fmaxf(fmaxf(-ds0c,0.0f)*is0,
                      fmaxf(fmaxf(-dsAc,0.0f)*isA, fmaxf(-dsBc,0.0f)*isB));
        sc_q3 = fmaxf(sc_q3, fmaxf(-dz0c,0.0f)*iz0);
        sc_q3 = fmaxf(sc_q3, fmaxf(-dzAc,0.0f)*izA);
        sc_q3 = fmaxf(sc_q3, fmaxf(-dzBc,0.0f)*izB);

        // ================= Round 3 (corrector dir + step, plain max) =======
        float dxc[VPT], ds1c[VPT], ds2c[VPT], dz1c[VPT], dz2c[VPT];
        {
            float qc = sc_q3;
#pragma unroll
            for (int k = 0; k < VPT; ++k) {
                float rsz1 = s1[k]*z1[k] + prod1[k] - smu;
                float rsz2 = s2[k]*z2[k] + prod2[k] - smu;
                float gc = gcb[k] - (T0c + fi[k]*TABc)*invD[k] - smu*cw[k];
                dxc[k]  = gc - (Y1c + fi[k]*Y2c) * invD[k];
                ds1c[k] = dxc[k] - rp1[k];
                ds2c[k] = -rp2[k] - dxc[k];
                dz1c[k] = -(rsz1 + z1[k]*ds1c[k]) * invs1[k];
                dz2c[k] = -(rsz2 + z2[k]*ds2c[k]) * invs2[k];
                qc = fmaxf(qc, fmaxf(fmaxf(-ds1c[k],0.0f)*invs1[k],
                                     fmaxf(-ds2c[k],0.0f)*invs2[k]));
                qc = fmaxf(qc, fmaxf(fmaxf(-dz1c[k],0.0f)*invz1[k],
                                     fmaxf(-dz2c[k],0.0f)*invz2[k]));
            }
            qc = bmax(qc);
            if (lane == 0) w3[wid] = qc;
        }
        __syncthreads();
        const float q = fmaxf(fmaxf(fmaxf(w3[0],w3[1]),fmaxf(w3[2],w3[3])),
                              fmaxf(fmaxf(w3[4],w3[5]),fmaxf(w3[6],w3[7])));

        const float st = (q > 0.0f) ? fminf(1.0f, nrcp(q)) : 1.0f;
        const float alpha = 0.99f * st;

        s0 += alpha*ds0c;  sA += alpha*dsAc;  sB += alpha*dsBc;
        z0 += alpha*dz0c;  zA += alpha*dzAc;  zB += alpha*dzBc;
#pragma unroll
        for (int k = 0; k < VPT; ++k) {
            xi[k] += alpha * dxc[k];
            s1[k] += alpha * ds1c[k];  z1[k] += alpha * dz1c[k];
            s2[k] += alpha * ds2c[k];  z2[k] += alpha * dz2c[k];
        }
    }

#pragma unroll
    for (int k = 0; k < VPT; ++k)
        out[i + k * T] = xi[k];
}

extern "C" void kernel_launch(void* const* d_in, const int* in_sizes, int n_in,
                              void* d_out, int out_size)
{
    const float* x    = (const float*)d_in[0];
    const int*   male = (const int*)d_in[1];
    float*       out  = (float*)d_out;
    pdip_kernel<<<1, T>>>(x, male, out);
}